// round 2
// baseline (speedup 1.0000x reference)
#include <cuda_runtime.h>
#include <math.h>

// ---------------- problem constants ----------------
#define Bb   4
#define Cc   64
#define Hh   5
#define Ww   5
#define Kk   3
#define Ee   12
#define NHh  4
#define DHh  3
#define FFf  24
#define HOo  3
#define WOo  3
#define Ll   9                   // HO*WO
#define Ss   (Bb*Cc*Kk*Kk)       // 2304  (sequence length for attention)
#define ROWS (Ss*Ll)             // 20736 (token rows)

// ---------------- scratch (device globals; no allocs allowed) ----------------
__device__ float g_seq[ROWS*Ee];          // residual input
__device__ float g_q[Ll*NHh*Ss*DHh];      // [l][h][s][d], pre-scaled by 1/sqrt(3)
__device__ float g_k[Ll*NHh*Ss*DHh];
__device__ float g_v[Ll*NHh*Ss*DHh];
__device__ float g_ctx[ROWS*Ee];          // attention output (pre out_proj)
__device__ float g_h1[ROWS*Ee];           // after LN1
__device__ float g_proj[ROWS];            // scalar per row, pre-fold

// ---------------- kernel 1: unfold + embeddings + QKV projection ----------------
__global__ void k_embed_qkv(const float* __restrict__ x,
                            const float* __restrict__ ce,
                            const float* __restrict__ pe,
                            const float* __restrict__ wqkv,   // (3E, E) row-major
                            const float* __restrict__ bqkv)   // (3E,)
{
    __shared__ float sw[3*Ee*Ee + 3*Ee];
    for (int i = threadIdx.x; i < 3*Ee*Ee; i += blockDim.x) sw[i] = wqkv[i];
    for (int i = threadIdx.x; i < 3*Ee;    i += blockDim.x) sw[3*Ee*Ee + i] = bqkv[i];
    __syncthreads();

    int row = blockIdx.x*blockDim.x + threadIdx.x;
    if (row >= ROWS) return;
    int s = row / Ll, l = row % Ll;
    int b   = s / (Cc*Kk*Kk);
    int rem = s % (Cc*Kk*Kk);
    int c = rem / (Kk*Kk), p = rem % (Kk*Kk);
    int i = p / Kk, j = p % Kk;
    int oi = l / WOo, oj = l % WOo;

    float xv = x[((b*Cc + c)*Hh + (i+oi))*Ww + (j+oj)];

    float r[Ee];
    #pragma unroll
    for (int e = 0; e < Ee; e++) {
        r[e] = ce[c*Ee + e] + pe[l*Ee + e] + xv;
        g_seq[row*Ee + e] = r[e];
    }

    const float qscale = 0.577350269189625764f;  // 1/sqrt(DH)

    // q
    #pragma unroll
    for (int e = 0; e < Ee; e++) {
        float acc = sw[3*Ee*Ee + e];
        #pragma unroll
        for (int f = 0; f < Ee; f++) acc += r[f] * sw[e*Ee + f];
        int h = e / DHh, d = e % DHh;
        g_q[((l*NHh + h)*Ss + s)*DHh + d] = acc * qscale;
    }
    // k
    #pragma unroll
    for (int e = 0; e < Ee; e++) {
        float acc = sw[3*Ee*Ee + Ee + e];
        #pragma unroll
        for (int f = 0; f < Ee; f++) acc += r[f] * sw[(Ee + e)*Ee + f];
        int h = e / DHh, d = e % DHh;
        g_k[((l*NHh + h)*Ss + s)*DHh + d] = acc;
    }
    // v
    #pragma unroll
    for (int e = 0; e < Ee; e++) {
        float acc = sw[3*Ee*Ee + 2*Ee + e];
        #pragma unroll
        for (int f = 0; f < Ee; f++) acc += r[f] * sw[(2*Ee + e)*Ee + f];
        int h = e / DHh, d = e % DHh;
        g_v[((l*NHh + h)*Ss + s)*DHh + d] = acc;
    }
}

// ---------------- kernel 2: streaming softmax attention ----------------
// grid: (36 combos, 18 query chunks), block: 128 threads, 1 query row / thread.
// K/V for the combo staged in smem in two 1152-row chunks (2*2*13.8KB = 27.6KB*... <48KB).
#define QPB    128
#define TCHUNK 1152

__global__ void k_attn()
{
    __shared__ float ks[TCHUNK*DHh];
    __shared__ float vs[TCHUNK*DHh];

    int combo = blockIdx.x;                 // = l*NHh + h
    int s = blockIdx.y*QPB + threadIdx.x;   // query index, always < Ss

    const float* __restrict__ kg = g_k + combo*Ss*DHh;
    const float* __restrict__ vg = g_v + combo*Ss*DHh;
    const float* __restrict__ qg = g_q + (combo*Ss + s)*DHh;

    float q0 = qg[0], q1 = qg[1], q2 = qg[2];
    float sum = 0.f, a0 = 0.f, a1 = 0.f, a2 = 0.f;

    for (int base = 0; base < Ss; base += TCHUNK) {
        __syncthreads();   // protect previous chunk's consumers
        for (int i = threadIdx.x; i < TCHUNK*DHh; i += QPB) {
            ks[i] = kg[base*DHh + i];
            vs[i] = vg[base*DHh + i];
        }
        __syncthreads();

        #pragma unroll 8
        for (int t = 0; t < TCHUNK; t++) {
            float sc = q0*ks[t*3] + q1*ks[t*3+1] + q2*ks[t*3+2];
            float w  = __expf(sc);           // scores small; no max-sub needed
            sum += w;
            a0 += w * vs[t*3];
            a1 += w * vs[t*3+1];
            a2 += w * vs[t*3+2];
        }
    }

    float inv = 1.f / sum;
    int l = combo / NHh, h = combo % NHh;
    float* out = g_ctx + (s*Ll + l)*Ee + h*DHh;
    out[0] = a0*inv; out[1] = a1*inv; out[2] = a2*inv;
}

// ---------------- kernel 3: out_proj + residual + LN1 ----------------
__global__ void k_outproj_ln1(const float* __restrict__ wo,   // (E,E)
                              const float* __restrict__ bo,
                              const float* __restrict__ g1,   // ln1_w
                              const float* __restrict__ b1)   // ln1_b
{
    __shared__ float sw[Ee*Ee], sb[Ee], sg[Ee], sbt[Ee];
    for (int i = threadIdx.x; i < Ee*Ee; i += blockDim.x) sw[i] = wo[i];
    if (threadIdx.x < Ee) {
        sb[threadIdx.x]  = bo[threadIdx.x];
        sg[threadIdx.x]  = g1[threadIdx.x];
        sbt[threadIdx.x] = b1[threadIdx.x];
    }
    __syncthreads();

    int row = blockIdx.x*blockDim.x + threadIdx.x;
    if (row >= ROWS) return;

    float cx[Ee];
    #pragma unroll
    for (int e = 0; e < Ee; e++) cx[e] = g_ctx[row*Ee + e];

    float t[Ee]; float mu = 0.f;
    #pragma unroll
    for (int e = 0; e < Ee; e++) {
        float acc = sb[e];
        #pragma unroll
        for (int f = 0; f < Ee; f++) acc += cx[f] * sw[e*Ee + f];
        t[e] = g_seq[row*Ee + e] + acc;
        mu += t[e];
    }
    mu *= (1.f/Ee);
    float var = 0.f;
    #pragma unroll
    for (int e = 0; e < Ee; e++) { float d = t[e]-mu; var += d*d; }
    var *= (1.f/Ee);
    float rs = rsqrtf(var + 1e-5f);
    #pragma unroll
    for (int e = 0; e < Ee; e++)
        g_h1[row*Ee + e] = (t[e]-mu)*rs*sg[e] + sbt[e];
}

// ---------------- kernel 4: FFN + residual + LN2 + final linear ----------------
__global__ void k_ffn_ln2_lin(const float* __restrict__ f1w, const float* __restrict__ f1b,
                              const float* __restrict__ f2w, const float* __restrict__ f2b,
                              const float* __restrict__ g2,  const float* __restrict__ b2,
                              const float* __restrict__ lw,  const float* __restrict__ lb)
{
    __shared__ float s1[FFf*Ee], s1b[FFf], s2[Ee*FFf], s2b[Ee];
    __shared__ float sg[Ee], sbt[Ee], slw[Ee], slb;
    for (int i = threadIdx.x; i < FFf*Ee; i += blockDim.x) { s1[i] = f1w[i]; s2[i] = f2w[i]; }
    if (threadIdx.x < FFf) s1b[threadIdx.x] = f1b[threadIdx.x];
    if (threadIdx.x < Ee) {
        s2b[threadIdx.x] = f2b[threadIdx.x];
        sg[threadIdx.x]  = g2[threadIdx.x];
        sbt[threadIdx.x] = b2[threadIdx.x];
        slw[threadIdx.x] = lw[threadIdx.x];
    }
    if (threadIdx.x == 0) slb = lb[0];
    __syncthreads();

    int row = blockIdx.x*blockDim.x + threadIdx.x;
    if (row >= ROWS) return;

    float h[Ee];
    #pragma unroll
    for (int e = 0; e < Ee; e++) h[e] = g_h1[row*Ee + e];

    float hid[FFf];
    #pragma unroll
    for (int f = 0; f < FFf; f++) {
        float acc = s1b[f];
        #pragma unroll
        for (int e = 0; e < Ee; e++) acc += h[e] * s1[f*Ee + e];
        hid[f] = fmaxf(acc, 0.f);
    }

    float t[Ee]; float mu = 0.f;
    #pragma unroll
    for (int e = 0; e < Ee; e++) {
        float acc = s2b[e];
        #pragma unroll
        for (int f = 0; f < FFf; f++) acc += hid[f] * s2[e*FFf + f];
        t[e] = h[e] + acc;
        mu += t[e];
    }
    mu *= (1.f/Ee);
    float var = 0.f;
    #pragma unroll
    for (int e = 0; e < Ee; e++) { float d = t[e]-mu; var += d*d; }
    var *= (1.f/Ee);
    float rs = rsqrtf(var + 1e-5f);

    float proj = slb;
    #pragma unroll
    for (int e = 0; e < Ee; e++)
        proj += ((t[e]-mu)*rs*sg[e] + sbt[e]) * slw[e];

    g_proj[row] = proj;
}

// ---------------- kernel 5: fold (gather-add) ----------------
__global__ void k_fold(float* __restrict__ y)
{
    int idx = blockIdx.x*blockDim.x + threadIdx.x;
    if (idx >= Bb*Cc*Hh*Ww) return;
    int xx = idx % Ww;
    int yy = (idx / Ww) % Hh;
    int c  = (idx / (Ww*Hh)) % Cc;
    int b  =  idx / (Ww*Hh*Cc);

    float acc = 0.f;
    #pragma unroll
    for (int i = 0; i < Kk; i++) {
        int oi = yy - i;
        if (oi < 0 || oi >= HOo) continue;
        #pragma unroll
        for (int j = 0; j < Kk; j++) {
            int oj = xx - j;
            if (oj < 0 || oj >= WOo) continue;
            int s = (b*Cc + c)*(Kk*Kk) + i*Kk + j;
            int l = oi*WOo + oj;
            acc += g_proj[s*Ll + l];
        }
    }
    y[idx] = acc;
}

// ---------------- launch ----------------
extern "C" void kernel_launch(void* const* d_in, const int* in_sizes, int n_in,
                              void* d_out, int out_size)
{
    const float* x    = (const float*)d_in[0];
    const float* ce   = (const float*)d_in[1];
    const float* pe   = (const float*)d_in[2];
    const float* ipw  = (const float*)d_in[3];
    const float* ipb  = (const float*)d_in[4];
    const float* opw  = (const float*)d_in[5];
    const float* opb  = (const float*)d_in[6];
    const float* ln1w = (const float*)d_in[7];
    const float* ln1b = (const float*)d_in[8];
    const float* f1w  = (const float*)d_in[9];
    const float* f1b  = (const float*)d_in[10];
    const float* f2w  = (const float*)d_in[11];
    const float* f2b  = (const float*)d_in[12];
    const float* ln2w = (const float*)d_in[13];
    const float* ln2b = (const float*)d_in[14];
    const float* lw   = (const float*)d_in[15];
    const float* lb   = (const float*)d_in[16];
    float* y = (float*)d_out;

    k_embed_qkv<<<(ROWS + 255)/256, 256>>>(x, ce, pe, ipw, ipb);
    dim3 agrid(Ll*NHh, Ss/QPB);
    k_attn<<<agrid, QPB>>>();
    k_outproj_ln1<<<(ROWS + 255)/256, 256>>>(opw, opb, ln1w, ln1b);
    k_ffn_ln2_lin<<<(ROWS + 255)/256, 256>>>(f1w, f1b, f2w, f2b, ln2w, ln2b, lw, lb);
    k_fold<<<(Bb*Cc*Hh*Ww + 255)/256, 256>>>(y);
}

// round 3
// speedup vs baseline: 1.0009x; 1.0009x over previous
#include <cuda_runtime.h>
#include <math.h>

// ---------------- problem constants ----------------
#define Bb   4
#define Cc   64
#define Hh   5
#define Ww   5
#define Kk   3
#define Ee   12
#define NHh  4
#define DHh  3
#define FFf  24
#define HOo  3
#define WOo  3
#define Ll   9                   // HO*WO
#define Ss   (Bb*Cc*Kk*Kk)       // 2304  (sequence length for attention)
#define ROWS (Ss*Ll)             // 20736 (token rows)
#define NC   (Ll*NHh)            // 36 (l,h) combos

// ---------------- scratch (device globals; no allocs allowed) ----------------
__device__ float  g_seq[ROWS*Ee];       // residual input
__device__ float  g_q[NC*Ss*DHh];       // [combo][s][d], pre-scaled by log2(e)/sqrt(3)
__device__ float4 g_kv[NC*Ss*2];        // [combo][s][{k0k1k2_, v0v1v2_}]
__device__ float  g_ctx[ROWS*Ee];       // attention output (pre out_proj)
__device__ float  g_proj[ROWS];         // scalar per row, pre-fold

__device__ __forceinline__ float ex2(float x) {
    float r;
    asm("ex2.approx.f32 %0, %1;" : "=f"(r) : "f"(x));
    return r;
}

// ---------------- kernel 1: unfold + embeddings + QKV projection ----------------
__global__ void k_embed_qkv(const float* __restrict__ x,
                            const float* __restrict__ ce,
                            const float* __restrict__ pe,
                            const float* __restrict__ wqkv,   // (3E, E) row-major
                            const float* __restrict__ bqkv)   // (3E,)
{
    __shared__ float sw[3*Ee*Ee + 3*Ee];
    for (int i = threadIdx.x; i < 3*Ee*Ee; i += blockDim.x) sw[i] = wqkv[i];
    for (int i = threadIdx.x; i < 3*Ee;    i += blockDim.x) sw[3*Ee*Ee + i] = bqkv[i];
    __syncthreads();

    int row = blockIdx.x*blockDim.x + threadIdx.x;
    if (row >= ROWS) return;
    int s = row / Ll, l = row % Ll;
    int b   = s / (Cc*Kk*Kk);
    int rem = s % (Cc*Kk*Kk);
    int c = rem / (Kk*Kk), p = rem % (Kk*Kk);
    int i = p / Kk, j = p % Kk;
    int oi = l / WOo, oj = l % WOo;

    float xv = x[((b*Cc + c)*Hh + (i+oi))*Ww + (j+oj)];

    float r[Ee];
    #pragma unroll
    for (int e = 0; e < Ee; e++) {
        r[e] = ce[c*Ee + e] + pe[l*Ee + e] + xv;
        g_seq[row*Ee + e] = r[e];
    }

    // q scale: (1/sqrt(DH)) * log2(e)  -> later use 2^x == e^(x/log2e)
    const float qscale = 0.57735026918962576f * 1.4426950408889634f;

    float qv[Ee], kv[Ee], vv[Ee];
    #pragma unroll
    for (int e = 0; e < Ee; e++) {
        float aq = sw[3*Ee*Ee + e];
        float ak = sw[3*Ee*Ee + Ee + e];
        float av = sw[3*Ee*Ee + 2*Ee + e];
        #pragma unroll
        for (int f = 0; f < Ee; f++) {
            aq += r[f] * sw[e*Ee + f];
            ak += r[f] * sw[(Ee + e)*Ee + f];
            av += r[f] * sw[(2*Ee + e)*Ee + f];
        }
        qv[e] = aq * qscale; kv[e] = ak; vv[e] = av;
    }

    #pragma unroll
    for (int h = 0; h < NHh; h++) {
        int combo = l*NHh + h;
        float* qo = g_q + (combo*Ss + s)*DHh;
        qo[0] = qv[h*3]; qo[1] = qv[h*3+1]; qo[2] = qv[h*3+2];
        g_kv[(combo*Ss + s)*2 + 0] = make_float4(kv[h*3], kv[h*3+1], kv[h*3+2], 0.f);
        g_kv[(combo*Ss + s)*2 + 1] = make_float4(vv[h*3], vv[h*3+1], vv[h*3+2], 0.f);
    }
}

// ---------------- kernel 2: streaming softmax attention ----------------
// grid: (36 combos, 9 query chunks), block: 128 threads, 2 queries / thread.
#define QPB    128
#define QPT    2
#define TCHUNK 1152

__global__ void k_attn()
{
    __shared__ float4 kvs[TCHUNK*2];   // 36 KB

    int combo = blockIdx.x;
    int sA = blockIdx.y*(QPB*QPT) + threadIdx.x;   // query A
    int sB = sA + QPB;                              // query B

    const float4* __restrict__ kvg = g_kv + combo*Ss*2;
    const float*  __restrict__ qgA = g_q + (combo*Ss + sA)*DHh;
    const float*  __restrict__ qgB = g_q + (combo*Ss + sB)*DHh;

    float qA0 = qgA[0], qA1 = qgA[1], qA2 = qgA[2];
    float qB0 = qgB[0], qB1 = qgB[1], qB2 = qgB[2];
    float sumA = 0.f, aA0 = 0.f, aA1 = 0.f, aA2 = 0.f;
    float sumB = 0.f, aB0 = 0.f, aB1 = 0.f, aB2 = 0.f;

    for (int base = 0; base < Ss; base += TCHUNK) {
        __syncthreads();
        for (int i = threadIdx.x; i < TCHUNK*2; i += QPB)
            kvs[i] = kvg[base*2 + i];
        __syncthreads();

        #pragma unroll 4
        for (int t = 0; t < TCHUNK; t++) {
            float4 kr = kvs[2*t];
            float4 vr = kvs[2*t + 1];
            float scA = qA0*kr.x + qA1*kr.y + qA2*kr.z;
            float scB = qB0*kr.x + qB1*kr.y + qB2*kr.z;
            float wA = ex2(scA);
            float wB = ex2(scB);
            sumA += wA; aA0 += wA*vr.x; aA1 += wA*vr.y; aA2 += wA*vr.z;
            sumB += wB; aB0 += wB*vr.x; aB1 += wB*vr.y; aB2 += wB*vr.z;
        }
    }

    int l = combo / NHh, h = combo % NHh;
    float invA = 1.f / sumA;
    float invB = 1.f / sumB;
    float* outA = g_ctx + (sA*Ll + l)*Ee + h*DHh;
    float* outB = g_ctx + (sB*Ll + l)*Ee + h*DHh;
    outA[0] = aA0*invA; outA[1] = aA1*invA; outA[2] = aA2*invA;
    outB[0] = aB0*invB; outB[1] = aB1*invB; outB[2] = aB2*invB;
}

// ---------------- kernel 3: out_proj + LN1 + FFN + LN2 + linear (fused, row-local) ----------------
__global__ void k_post(const float* __restrict__ wo, const float* __restrict__ bo,
                       const float* __restrict__ g1, const float* __restrict__ b1,
                       const float* __restrict__ f1w, const float* __restrict__ f1b,
                       const float* __restrict__ f2w, const float* __restrict__ f2b,
                       const float* __restrict__ g2, const float* __restrict__ b2,
                       const float* __restrict__ lw, const float* __restrict__ lb)
{
    __shared__ float swo[Ee*Ee], sbo[Ee], sg1[Ee], sb1[Ee];
    __shared__ float s1[FFf*Ee], s1b[FFf], s2[Ee*FFf], s2b[Ee];
    __shared__ float sg2[Ee], sb2[Ee], slw[Ee], slb;
    for (int i = threadIdx.x; i < Ee*Ee; i += blockDim.x) swo[i] = wo[i];
    for (int i = threadIdx.x; i < FFf*Ee; i += blockDim.x) { s1[i] = f1w[i]; s2[i] = f2w[i]; }
    if (threadIdx.x < FFf) s1b[threadIdx.x] = f1b[threadIdx.x];
    if (threadIdx.x < Ee) {
        sbo[threadIdx.x] = bo[threadIdx.x];
        sg1[threadIdx.x] = g1[threadIdx.x];
        sb1[threadIdx.x] = b1[threadIdx.x];
        s2b[threadIdx.x] = f2b[threadIdx.x];
        sg2[threadIdx.x] = g2[threadIdx.x];
        sb2[threadIdx.x] = b2[threadIdx.x];
        slw[threadIdx.x] = lw[threadIdx.x];
    }
    if (threadIdx.x == 0) slb = lb[0];
    __syncthreads();

    int row = blockIdx.x*blockDim.x + threadIdx.x;
    if (row >= ROWS) return;

    float cx[Ee];
    #pragma unroll
    for (int e = 0; e < Ee; e++) cx[e] = g_ctx[row*Ee + e];

    // out_proj + residual
    float t[Ee]; float mu = 0.f;
    #pragma unroll
    for (int e = 0; e < Ee; e++) {
        float acc = sbo[e];
        #pragma unroll
        for (int f = 0; f < Ee; f++) acc += cx[f] * swo[e*Ee + f];
        t[e] = g_seq[row*Ee + e] + acc;
        mu += t[e];
    }
    mu *= (1.f/Ee);
    float var = 0.f;
    #pragma unroll
    for (int e = 0; e < Ee; e++) { float d = t[e]-mu; var += d*d; }
    var *= (1.f/Ee);
    float rs = rsqrtf(var + 1e-5f);

    float h1[Ee];
    #pragma unroll
    for (int e = 0; e < Ee; e++) h1[e] = (t[e]-mu)*rs*sg1[e] + sb1[e];

    // FFN
    float hid[FFf];
    #pragma unroll
    for (int f = 0; f < FFf; f++) {
        float acc = s1b[f];
        #pragma unroll
        for (int e = 0; e < Ee; e++) acc += h1[e] * s1[f*Ee + e];
        hid[f] = fmaxf(acc, 0.f);
    }

    float mu2 = 0.f;
    #pragma unroll
    for (int e = 0; e < Ee; e++) {
        float acc = s2b[e];
        #pragma unroll
        for (int f = 0; f < FFf; f++) acc += hid[f] * s2[e*FFf + f];
        t[e] = h1[e] + acc;
        mu2 += t[e];
    }
    mu2 *= (1.f/Ee);
    float var2 = 0.f;
    #pragma unroll
    for (int e = 0; e < Ee; e++) { float d = t[e]-mu2; var2 += d*d; }
    var2 *= (1.f/Ee);
    float rs2 = rsqrtf(var2 + 1e-5f);

    float proj = slb;
    #pragma unroll
    for (int e = 0; e < Ee; e++)
        proj += ((t[e]-mu2)*rs2*sg2[e] + sb2[e]) * slw[e];

    g_proj[row] = proj;
}

// ---------------- kernel 4: fold (gather-add) ----------------
__global__ void k_fold(float* __restrict__ y)
{
    int idx = blockIdx.x*blockDim.x + threadIdx.x;
    if (idx >= Bb*Cc*Hh*Ww) return;
    int xx = idx % Ww;
    int yy = (idx / Ww) % Hh;
    int c  = (idx / (Ww*Hh)) % Cc;
    int b  =  idx / (Ww*Hh*Cc);

    float acc = 0.f;
    #pragma unroll
    for (int i = 0; i < Kk; i++) {
        int oi = yy - i;
        if (oi < 0 || oi >= HOo) continue;
        #pragma unroll
        for (int j = 0; j < Kk; j++) {
            int oj = xx - j;
            if (oj < 0 || oj >= WOo) continue;
            int s = (b*Cc + c)*(Kk*Kk) + i*Kk + j;
            int l = oi*WOo + oj;
            acc += g_proj[s*Ll + l];
        }
    }
    y[idx] = acc;
}

// ---------------- launch ----------------
extern "C" void kernel_launch(void* const* d_in, const int* in_sizes, int n_in,
                              void* d_out, int out_size)
{
    const float* x    = (const float*)d_in[0];
    const float* ce   = (const float*)d_in[1];
    const float* pe   = (const float*)d_in[2];
    const float* ipw  = (const float*)d_in[3];
    const float* ipb  = (const float*)d_in[4];
    const float* opw  = (const float*)d_in[5];
    const float* opb  = (const float*)d_in[6];
    const float* ln1w = (const float*)d_in[7];
    const float* ln1b = (const float*)d_in[8];
    const float* f1w  = (const float*)d_in[9];
    const float* f1b  = (const float*)d_in[10];
    const float* f2w  = (const float*)d_in[11];
    const float* f2b  = (const float*)d_in[12];
    const float* ln2w = (const float*)d_in[13];
    const float* ln2b = (const float*)d_in[14];
    const float* lw   = (const float*)d_in[15];
    const float* lb   = (const float*)d_in[16];
    float* y = (float*)d_out;

    k_embed_qkv<<<ROWS/128, 128>>>(x, ce, pe, ipw, ipb);
    dim3 agrid(NC, Ss/(QPB*QPT));
    k_attn<<<agrid, QPB>>>();
    k_post<<<ROWS/128, 128>>>(opw, opb, ln1w, ln1b, f1w, f1b, f2w, f2b, ln2w, ln2b, lw, lb);
    k_fold<<<(Bb*Cc*Hh*Ww + 127)/128, 128>>>(y);
}

// round 4
// speedup vs baseline: 1.1946x; 1.1935x over previous
#include <cuda_runtime.h>
#include <math.h>

typedef unsigned long long ull;

// ---------------- problem constants ----------------
#define Bb   4
#define Cc   64
#define Hh   5
#define Ww   5
#define Kk   3
#define Ee   12
#define NHh  4
#define DHh  3
#define FFf  24
#define HOo  3
#define WOo  3
#define Ll   9
#define Ss   (Bb*Cc*Kk*Kk)       // 2304
#define ROWS (Ss*Ll)             // 20736
#define NC   (Ll*NHh)            // 36

// attention tiling
#define QPB   64                 // threads per attn block
#define QPT   4                  // queries per thread (2 packed pairs)
#define NQC   9                  // query chunks (2304 / (64*4))
#define NTC   4                  // t-splits
#define TCH   (Ss/NTC)           // 576 t per block

// ---------------- scratch ----------------
__device__ float      g_seq[ROWS*Ee];
__device__ float      g_q[NC*Ss*DHh];          // scaled by log2(e)/sqrt(3)
__device__ ulonglong2 g_kvd[NC*Ss*3];          // dup-packed: {kx,kx,ky,ky},{kz,kz,vx,vx},{vy,vy,vz,vz}
__device__ float4     g_part[NC*Ss*NTC];       // {sum, a0, a1, a2} partials
__device__ float      g_proj[ROWS];

// ---------------- packed f32x2 helpers ----------------
__device__ __forceinline__ ull ffma2(ull a, ull b, ull c) {
    ull d; asm("fma.rn.f32x2 %0, %1, %2, %3;" : "=l"(d) : "l"(a), "l"(b), "l"(c)); return d;
}
__device__ __forceinline__ ull fmul2(ull a, ull b) {
    ull d; asm("mul.rn.f32x2 %0, %1, %2;" : "=l"(d) : "l"(a), "l"(b)); return d;
}
__device__ __forceinline__ ull fadd2(ull a, ull b) {
    ull d; asm("add.rn.f32x2 %0, %1, %2;" : "=l"(d) : "l"(a), "l"(b)); return d;
}
__device__ __forceinline__ ull pack2(float lo, float hi) {
    ull d; asm("mov.b64 %0, {%1, %2};" : "=l"(d) : "f"(lo), "f"(hi)); return d;
}
__device__ __forceinline__ void unpack2(ull v, float& lo, float& hi) {
    asm("mov.b64 {%0, %1}, %2;" : "=f"(lo), "=f"(hi) : "l"(v));
}
__device__ __forceinline__ ull ex2pair(ull s) {
    ull r;
    asm("{\n\t"
        ".reg .f32 lo, hi;\n\t"
        "mov.b64 {lo, hi}, %1;\n\t"
        "ex2.approx.f32 lo, lo;\n\t"
        "ex2.approx.f32 hi, hi;\n\t"
        "mov.b64 %0, {lo, hi};\n\t"
        "}" : "=l"(r) : "l"(s));
    return r;
}

// ---------------- kernel 1: unfold + embeddings + QKV projection ----------------
__global__ void k_embed_qkv(const float* __restrict__ x,
                            const float* __restrict__ ce,
                            const float* __restrict__ pe,
                            const float* __restrict__ wqkv,
                            const float* __restrict__ bqkv)
{
    __shared__ float sw[3*Ee*Ee + 3*Ee];
    for (int i = threadIdx.x; i < 3*Ee*Ee; i += blockDim.x) sw[i] = wqkv[i];
    for (int i = threadIdx.x; i < 3*Ee;    i += blockDim.x) sw[3*Ee*Ee + i] = bqkv[i];
    __syncthreads();

    int row = blockIdx.x*blockDim.x + threadIdx.x;
    if (row >= ROWS) return;
    int s = row / Ll, l = row % Ll;
    int b   = s / (Cc*Kk*Kk);
    int rem = s % (Cc*Kk*Kk);
    int c = rem / (Kk*Kk), p = rem % (Kk*Kk);
    int i = p / Kk, j = p % Kk;
    int oi = l / WOo, oj = l % WOo;

    float xv = x[((b*Cc + c)*Hh + (i+oi))*Ww + (j+oj)];

    float r[Ee];
    #pragma unroll
    for (int e = 0; e < Ee; e++) {
        r[e] = ce[c*Ee + e] + pe[l*Ee + e] + xv;
        g_seq[row*Ee + e] = r[e];
    }

    // q scale: (1/sqrt(DH)) * log2(e); inner loop uses ex2
    const float qscale = 0.57735026918962576f * 1.4426950408889634f;

    float qv[Ee], kv[Ee], vv[Ee];
    #pragma unroll
    for (int e = 0; e < Ee; e++) {
        float aq = sw[3*Ee*Ee + e];
        float ak = sw[3*Ee*Ee + Ee + e];
        float av = sw[3*Ee*Ee + 2*Ee + e];
        #pragma unroll
        for (int f = 0; f < Ee; f++) {
            aq += r[f] * sw[e*Ee + f];
            ak += r[f] * sw[(Ee + e)*Ee + f];
            av += r[f] * sw[(2*Ee + e)*Ee + f];
        }
        qv[e] = aq * qscale; kv[e] = ak; vv[e] = av;
    }

    float4* kvd = (float4*)g_kvd;
    #pragma unroll
    for (int h = 0; h < NHh; h++) {
        int combo = l*NHh + h;
        float* qo = g_q + (combo*Ss + s)*DHh;
        qo[0] = qv[h*3]; qo[1] = qv[h*3+1]; qo[2] = qv[h*3+2];
        int idx = (combo*Ss + s)*3;
        float k0 = kv[h*3], k1 = kv[h*3+1], k2 = kv[h*3+2];
        float v0 = vv[h*3], v1 = vv[h*3+1], v2 = vv[h*3+2];
        kvd[idx+0] = make_float4(k0, k0, k1, k1);
        kvd[idx+1] = make_float4(k2, k2, v0, v0);
        kvd[idx+2] = make_float4(v1, v1, v2, v2);
    }
}

// ---------------- kernel 2: attention partials ----------------
// grid (36 combos, 9 q-chunks, 4 t-chunks), 64 threads, 4 queries/thread.
__global__ void k_attn()
{
    __shared__ ulonglong2 kvs[TCH*3];   // 27 KB

    int combo = blockIdx.x;
    int tid   = threadIdx.x;
    int s0 = blockIdx.y*(QPB*QPT) + tid;       // queries s0, s0+64, s0+128, s0+192
    int tb = blockIdx.z*TCH;

    // stage K/V chunk (pre-duplicated pairs)
    {
        const ulonglong2* src = g_kvd + (combo*Ss + tb)*3;
        for (int i = tid; i < TCH*3; i += QPB) kvs[i] = src[i];
    }

    // load 4 queries, pack as 2 pairs
    const float* qg = g_q + (combo*Ss + s0)*DHh;
    float qa0 = qg[0],        qa1 = qg[1],        qa2 = qg[2];
    float qb0 = qg[64*3],     qb1 = qg[64*3+1],   qb2 = qg[64*3+2];
    float qc0 = qg[128*3],    qc1 = qg[128*3+1],  qc2 = qg[128*3+2];
    float qd0 = qg[192*3],    qd1 = qg[192*3+1],  qd2 = qg[192*3+2];
    ull p0x = pack2(qa0, qb0), p0y = pack2(qa1, qb1), p0z = pack2(qa2, qb2);
    ull p1x = pack2(qc0, qd0), p1y = pack2(qc1, qd1), p1z = pack2(qc2, qd2);

    ull sum0 = 0, a00 = 0, a01 = 0, a02 = 0;   // pair0 accums (packed {A,B})
    ull sum1 = 0, a10 = 0, a11 = 0, a12 = 0;   // pair1 accums (packed {C,D})

    __syncthreads();

    #pragma unroll 4
    for (int t = 0; t < TCH; t++) {
        ulonglong2 u0 = kvs[3*t];     // {kx2, ky2}
        ulonglong2 u1 = kvs[3*t+1];   // {kz2, vx2}
        ulonglong2 u2 = kvs[3*t+2];   // {vy2, vz2}

        ull sA = ffma2(p0x, u0.x, ffma2(p0y, u0.y, fmul2(p0z, u1.x)));
        ull sB = ffma2(p1x, u0.x, ffma2(p1y, u0.y, fmul2(p1z, u1.x)));
        ull wA = ex2pair(sA);
        ull wB = ex2pair(sB);
        sum0 = fadd2(sum0, wA);
        a00  = ffma2(wA, u1.y, a00);
        a01  = ffma2(wA, u2.x, a01);
        a02  = ffma2(wA, u2.y, a02);
        sum1 = fadd2(sum1, wB);
        a10  = ffma2(wB, u1.y, a10);
        a11  = ffma2(wB, u2.x, a11);
        a12  = ffma2(wB, u2.y, a12);
    }

    // write partials {sum, a0, a1, a2} per query
    int tc = blockIdx.z;
    float sA, sB, x0A, x0B, x1A, x1B, x2A, x2B;

    unpack2(sum0, sA, sB); unpack2(a00, x0A, x0B); unpack2(a01, x1A, x1B); unpack2(a02, x2A, x2B);
    g_part[(combo*Ss + s0      )*NTC + tc] = make_float4(sA, x0A, x1A, x2A);
    g_part[(combo*Ss + s0 + 64 )*NTC + tc] = make_float4(sB, x0B, x1B, x2B);

    unpack2(sum1, sA, sB); unpack2(a10, x0A, x0B); unpack2(a11, x1A, x1B); unpack2(a12, x2A, x2B);
    g_part[(combo*Ss + s0 + 128)*NTC + tc] = make_float4(sA, x0A, x1A, x2A);
    g_part[(combo*Ss + s0 + 192)*NTC + tc] = make_float4(sB, x0B, x1B, x2B);
}

// ---------------- kernel 3: combine + out_proj + LN1 + FFN + LN2 + linear ----------------
__global__ void k_post(const float* __restrict__ wo, const float* __restrict__ bo,
                       const float* __restrict__ g1, const float* __restrict__ b1,
                       const float* __restrict__ f1w, const float* __restrict__ f1b,
                       const float* __restrict__ f2w, const float* __restrict__ f2b,
                       const float* __restrict__ g2, const float* __restrict__ b2,
                       const float* __restrict__ lw, const float* __restrict__ lb)
{
    __shared__ float swo[Ee*Ee], sbo[Ee], sg1[Ee], sb1[Ee];
    __shared__ float s1[FFf*Ee], s1b[FFf], s2[Ee*FFf], s2b[Ee];
    __shared__ float sg2[Ee], sb2[Ee], slw[Ee], slb;
    for (int i = threadIdx.x; i < Ee*Ee; i += blockDim.x) swo[i] = wo[i];
    for (int i = threadIdx.x; i < FFf*Ee; i += blockDim.x) { s1[i] = f1w[i]; s2[i] = f2w[i]; }
    if (threadIdx.x < FFf) s1b[threadIdx.x] = f1b[threadIdx.x];
    if (threadIdx.x < Ee) {
        sbo[threadIdx.x] = bo[threadIdx.x];
        sg1[threadIdx.x] = g1[threadIdx.x];
        sb1[threadIdx.x] = b1[threadIdx.x];
        s2b[threadIdx.x] = f2b[threadIdx.x];
        sg2[threadIdx.x] = g2[threadIdx.x];
        sb2[threadIdx.x] = b2[threadIdx.x];
        slw[threadIdx.x] = lw[threadIdx.x];
    }
    if (threadIdx.x == 0) slb = lb[0];
    __syncthreads();

    int row = blockIdx.x*blockDim.x + threadIdx.x;
    if (row >= ROWS) return;
    int s = row / Ll, l = row % Ll;

    // combine attention partials -> ctx
    float cx[Ee];
    #pragma unroll
    for (int h = 0; h < NHh; h++) {
        int combo = l*NHh + h;
        const float4* pp = g_part + (combo*Ss + s)*NTC;
        float4 acc = pp[0];
        #pragma unroll
        for (int tc = 1; tc < NTC; tc++) {
            float4 q = pp[tc];
            acc.x += q.x; acc.y += q.y; acc.z += q.z; acc.w += q.w;
        }
        float inv = 1.f / acc.x;
        cx[h*3]   = acc.y * inv;
        cx[h*3+1] = acc.z * inv;
        cx[h*3+2] = acc.w * inv;
    }

    // out_proj + residual + LN1
    float t[Ee]; float mu = 0.f;
    #pragma unroll
    for (int e = 0; e < Ee; e++) {
        float acc = sbo[e];
        #pragma unroll
        for (int f = 0; f < Ee; f++) acc += cx[f] * swo[e*Ee + f];
        t[e] = g_seq[row*Ee + e] + acc;
        mu += t[e];
    }
    mu *= (1.f/Ee);
    float var = 0.f;
    #pragma unroll
    for (int e = 0; e < Ee; e++) { float d = t[e]-mu; var += d*d; }
    var *= (1.f/Ee);
    float rs = rsqrtf(var + 1e-5f);

    float h1[Ee];
    #pragma unroll
    for (int e = 0; e < Ee; e++) h1[e] = (t[e]-mu)*rs*sg1[e] + sb1[e];

    // FFN
    float hid[FFf];
    #pragma unroll
    for (int f = 0; f < FFf; f++) {
        float acc = s1b[f];
        #pragma unroll
        for (int e = 0; e < Ee; e++) acc += h1[e] * s1[f*Ee + e];
        hid[f] = fmaxf(acc, 0.f);
    }

    float mu2 = 0.f;
    #pragma unroll
    for (int e = 0; e < Ee; e++) {
        float acc = s2b[e];
        #pragma unroll
        for (int f = 0; f < FFf; f++) acc += hid[f] * s2[e*FFf + f];
        t[e] = h1[e] + acc;
        mu2 += t[e];
    }
    mu2 *= (1.f/Ee);
    float var2 = 0.f;
    #pragma unroll
    for (int e = 0; e < Ee; e++) { float d = t[e]-mu2; var2 += d*d; }
    var2 *= (1.f/Ee);
    float rs2 = rsqrtf(var2 + 1e-5f);

    float proj = slb;
    #pragma unroll
    for (int e = 0; e < Ee; e++)
        proj += ((t[e]-mu2)*rs2*sg2[e] + sb2[e]) * slw[e];

    g_proj[row] = proj;
}

// ---------------- kernel 4: fold (gather-add) ----------------
__global__ void k_fold(float* __restrict__ y)
{
    int idx = blockIdx.x*blockDim.x + threadIdx.x;
    if (idx >= Bb*Cc*Hh*Ww) return;
    int xx = idx % Ww;
    int yy = (idx / Ww) % Hh;
    int c  = (idx / (Ww*Hh)) % Cc;
    int b  =  idx / (Ww*Hh*Cc);

    float acc = 0.f;
    #pragma unroll
    for (int i = 0; i < Kk; i++) {
        int oi = yy - i;
        if (oi < 0 || oi >= HOo) continue;
        #pragma unroll
        for (int j = 0; j < Kk; j++) {
            int oj = xx - j;
            if (oj < 0 || oj >= WOo) continue;
            int s = (b*Cc + c)*(Kk*Kk) + i*Kk + j;
            int l = oi*WOo + oj;
            acc += g_proj[s*Ll + l];
        }
    }
    y[idx] = acc;
}

// ---------------- launch ----------------
extern "C" void kernel_launch(void* const* d_in, const int* in_sizes, int n_in,
                              void* d_out, int out_size)
{
    const float* x    = (const float*)d_in[0];
    const float* ce   = (const float*)d_in[1];
    const float* pe   = (const float*)d_in[2];
    const float* ipw  = (const float*)d_in[3];
    const float* ipb  = (const float*)d_in[4];
    const float* opw  = (const float*)d_in[5];
    const float* opb  = (const float*)d_in[6];
    const float* ln1w = (const float*)d_in[7];
    const float* ln1b = (const float*)d_in[8];
    const float* f1w  = (const float*)d_in[9];
    const float* f1b  = (const float*)d_in[10];
    const float* f2w  = (const float*)d_in[11];
    const float* f2b  = (const float*)d_in[12];
    const float* ln2w = (const float*)d_in[13];
    const float* ln2b = (const float*)d_in[14];
    const float* lw   = (const float*)d_in[15];
    const float* lb   = (const float*)d_in[16];
    float* y = (float*)d_out;

    k_embed_qkv<<<ROWS/128, 128>>>(x, ce, pe, ipw, ipb);
    dim3 agrid(NC, NQC, NTC);
    k_attn<<<agrid, QPB>>>();
    k_post<<<ROWS/128, 128>>>(opw, opb, ln1w, ln1b, f1w, f1b, f2w, f2b, ln2w, ln2b, lw, lb);
    k_fold<<<(Bb*Cc*Hh*Ww + 127)/128, 128>>>(y);
}

// round 5
// speedup vs baseline: 1.2610x; 1.0556x over previous
#include <cuda_runtime.h>
#include <math.h>

typedef unsigned long long ull;

// ---------------- problem constants ----------------
#define Bb   4
#define Cc   64
#define Hh   5
#define Ww   5
#define Kk   3
#define Ee   12
#define NHh  4
#define DHh  3
#define FFf  24
#define HOo  3
#define WOo  3
#define Ll   9
#define Ss   (Bb*Cc*Kk*Kk)       // 2304
#define ROWS (Ss*Ll)             // 20736
#define NC   (Ll*NHh)            // 36
#define YSZ  (Bb*Cc*Hh*Ww)       // 6400

// attention tiling
#define QPB   96                 // threads per attn block (3 warps)
#define QPT   8                  // queries per thread (4 packed pairs)
#define NQC   3                  // query chunks  (2304 / (96*8))
#define NTC   6                  // t-splits
#define TCH   (Ss/NTC)           // 384 t per block

// ---------------- scratch ----------------
__device__ float      g_seq[ROWS*Ee];
__device__ float      g_q[NC*Ss*DHh];          // scaled by log2(e)/sqrt(3)
__device__ ulonglong2 g_kvd[NC*Ss*3];          // dup-packed: {kx,kx,ky,ky},{kz,kz,vx,vx},{vy,vy,vz,vz}
__device__ float4     g_part[NC*Ss*NTC];       // {sum, a0, a1, a2} partials

// ---------------- packed f32x2 helpers ----------------
__device__ __forceinline__ ull ffma2(ull a, ull b, ull c) {
    ull d; asm("fma.rn.f32x2 %0, %1, %2, %3;" : "=l"(d) : "l"(a), "l"(b), "l"(c)); return d;
}
__device__ __forceinline__ ull fmul2(ull a, ull b) {
    ull d; asm("mul.rn.f32x2 %0, %1, %2;" : "=l"(d) : "l"(a), "l"(b)); return d;
}
__device__ __forceinline__ ull fadd2(ull a, ull b) {
    ull d; asm("add.rn.f32x2 %0, %1, %2;" : "=l"(d) : "l"(a), "l"(b)); return d;
}
__device__ __forceinline__ ull pack2(float lo, float hi) {
    ull d; asm("mov.b64 %0, {%1, %2};" : "=l"(d) : "f"(lo), "f"(hi)); return d;
}
__device__ __forceinline__ void unpack2(ull v, float& lo, float& hi) {
    asm("mov.b64 {%0, %1}, %2;" : "=f"(lo), "=f"(hi) : "l"(v));
}
__device__ __forceinline__ ull ex2pair(ull s) {
    ull r;
    asm("{\n\t"
        ".reg .f32 lo, hi;\n\t"
        "mov.b64 {lo, hi}, %1;\n\t"
        "ex2.approx.f32 lo, lo;\n\t"
        "ex2.approx.f32 hi, hi;\n\t"
        "mov.b64 %0, {lo, hi};\n\t"
        "}" : "=l"(r) : "l"(s));
    return r;
}

// ---------------- kernel 1: unfold + embeddings + QKV projection (+ zero y) ----------------
__global__ void k_embed_qkv(const float* __restrict__ x,
                            const float* __restrict__ ce,
                            const float* __restrict__ pe,
                            const float* __restrict__ wqkv,
                            const float* __restrict__ bqkv,
                            float* __restrict__ y)
{
    __shared__ float sw[3*Ee*Ee + 3*Ee];
    for (int i = threadIdx.x; i < 3*Ee*Ee; i += blockDim.x) sw[i] = wqkv[i];
    for (int i = threadIdx.x; i < 3*Ee;    i += blockDim.x) sw[3*Ee*Ee + i] = bqkv[i];
    __syncthreads();

    int row = blockIdx.x*blockDim.x + threadIdx.x;
    if (row >= ROWS) return;
    if (row < YSZ) y[row] = 0.f;          // zero output for later atomics

    int s = row / Ll, l = row % Ll;
    int b   = s / (Cc*Kk*Kk);
    int rem = s % (Cc*Kk*Kk);
    int c = rem / (Kk*Kk), p = rem % (Kk*Kk);
    int i = p / Kk, j = p % Kk;
    int oi = l / WOo, oj = l % WOo;

    float xv = x[((b*Cc + c)*Hh + (i+oi))*Ww + (j+oj)];

    float r[Ee];
    #pragma unroll
    for (int e = 0; e < Ee; e++) {
        r[e] = ce[c*Ee + e] + pe[l*Ee + e] + xv;
        g_seq[row*Ee + e] = r[e];
    }

    // q scale: (1/sqrt(DH)) * log2(e); inner loop uses ex2
    const float qscale = 0.57735026918962576f * 1.4426950408889634f;

    float qv[Ee], kv[Ee], vv[Ee];
    #pragma unroll
    for (int e = 0; e < Ee; e++) {
        float aq = sw[3*Ee*Ee + e];
        float ak = sw[3*Ee*Ee + Ee + e];
        float av = sw[3*Ee*Ee + 2*Ee + e];
        #pragma unroll
        for (int f = 0; f < Ee; f++) {
            aq += r[f] * sw[e*Ee + f];
            ak += r[f] * sw[(Ee + e)*Ee + f];
            av += r[f] * sw[(2*Ee + e)*Ee + f];
        }
        qv[e] = aq * qscale; kv[e] = ak; vv[e] = av;
    }

    float4* kvd = (float4*)g_kvd;
    #pragma unroll
    for (int h = 0; h < NHh; h++) {
        int combo = l*NHh + h;
        float* qo = g_q + (combo*Ss + s)*DHh;
        qo[0] = qv[h*3]; qo[1] = qv[h*3+1]; qo[2] = qv[h*3+2];
        int idx = (combo*Ss + s)*3;
        float k0 = kv[h*3], k1 = kv[h*3+1], k2 = kv[h*3+2];
        float v0 = vv[h*3], v1 = vv[h*3+1], v2 = vv[h*3+2];
        kvd[idx+0] = make_float4(k0, k0, k1, k1);
        kvd[idx+1] = make_float4(k2, k2, v0, v0);
        kvd[idx+2] = make_float4(v1, v1, v2, v2);
    }
}

// ---------------- kernel 2: attention partials ----------------
// grid (36 combos, 3 q-chunks, 6 t-chunks), 96 threads, 8 queries/thread (4 packed pairs).
__global__ void k_attn()
{
    __shared__ ulonglong2 kvs[TCH*3];   // 18 KB

    int combo = blockIdx.x;
    int tid   = threadIdx.x;
    int s0 = blockIdx.y*(QPB*QPT) + tid;       // queries s0 + 96*j, j=0..7
    int tb = blockIdx.z*TCH;

    // stage K/V chunk (pre-duplicated pairs)
    {
        const ulonglong2* src = g_kvd + (combo*Ss + tb)*3;
        for (int i = tid; i < TCH*3; i += QPB) kvs[i] = src[i];
    }

    // load 8 queries, pack as 4 pairs
    const float* qg = g_q + (combo*Ss + s0)*DHh;
    ull px[4], py[4], pz[4];
    #pragma unroll
    for (int pq = 0; pq < 4; pq++) {
        const float* qa = qg + (2*pq  )*QPB*DHh;
        const float* qb = qg + (2*pq+1)*QPB*DHh;
        px[pq] = pack2(qa[0], qb[0]);
        py[pq] = pack2(qa[1], qb[1]);
        pz[pq] = pack2(qa[2], qb[2]);
    }

    ull sum[4] = {0,0,0,0};
    ull a0[4]  = {0,0,0,0};
    ull a1[4]  = {0,0,0,0};
    ull a2[4]  = {0,0,0,0};

    __syncthreads();

    #pragma unroll 4
    for (int t = 0; t < TCH; t++) {
        ulonglong2 u0 = kvs[3*t];     // {kx2, ky2}
        ulonglong2 u1 = kvs[3*t+1];   // {kz2, vx2}
        ulonglong2 u2 = kvs[3*t+2];   // {vy2, vz2}

        #pragma unroll
        for (int pq = 0; pq < 4; pq++) {
            ull sc = ffma2(px[pq], u0.x, ffma2(py[pq], u0.y, fmul2(pz[pq], u1.x)));
            ull w  = ex2pair(sc);
            sum[pq] = fadd2(sum[pq], w);
            a0[pq]  = ffma2(w, u1.y, a0[pq]);
            a1[pq]  = ffma2(w, u2.x, a1[pq]);
            a2[pq]  = ffma2(w, u2.y, a2[pq]);
        }
    }

    int tc = blockIdx.z;
    #pragma unroll
    for (int pq = 0; pq < 4; pq++) {
        float sA, sB, x0A, x0B, x1A, x1B, x2A, x2B;
        unpack2(sum[pq], sA, sB);
        unpack2(a0[pq], x0A, x0B);
        unpack2(a1[pq], x1A, x1B);
        unpack2(a2[pq], x2A, x2B);
        int sa = s0 + (2*pq)*QPB;
        g_part[(combo*Ss + sa      )*NTC + tc] = make_float4(sA, x0A, x1A, x2A);
        g_part[(combo*Ss + sa + QPB)*NTC + tc] = make_float4(sB, x0B, x1B, x2B);
    }
}

// ---------------- kernel 3: combine + out_proj + LN1 + FFN + LN2 + linear + fold (atomic) ----------------
__global__ void k_post(const float* __restrict__ wo, const float* __restrict__ bo,
                       const float* __restrict__ g1, const float* __restrict__ b1,
                       const float* __restrict__ f1w, const float* __restrict__ f1b,
                       const float* __restrict__ f2w, const float* __restrict__ f2b,
                       const float* __restrict__ g2, const float* __restrict__ b2,
                       const float* __restrict__ lw, const float* __restrict__ lb,
                       float* __restrict__ y)
{
    __shared__ float swo[Ee*Ee], sbo[Ee], sg1[Ee], sb1[Ee];
    __shared__ float s1[FFf*Ee], s1b[FFf], s2[Ee*FFf], s2b[Ee];
    __shared__ float sg2[Ee], sb2[Ee], slw[Ee], slb;
    for (int i = threadIdx.x; i < Ee*Ee; i += blockDim.x) swo[i] = wo[i];
    for (int i = threadIdx.x; i < FFf*Ee; i += blockDim.x) { s1[i] = f1w[i]; s2[i] = f2w[i]; }
    if (threadIdx.x < FFf) s1b[threadIdx.x] = f1b[threadIdx.x];
    if (threadIdx.x < Ee) {
        sbo[threadIdx.x] = bo[threadIdx.x];
        sg1[threadIdx.x] = g1[threadIdx.x];
        sb1[threadIdx.x] = b1[threadIdx.x];
        s2b[threadIdx.x] = f2b[threadIdx.x];
        sg2[threadIdx.x] = g2[threadIdx.x];
        sb2[threadIdx.x] = b2[threadIdx.x];
        slw[threadIdx.x] = lw[threadIdx.x];
    }
    if (threadIdx.x == 0) slb = lb[0];
    __syncthreads();

    int row = blockIdx.x*blockDim.x + threadIdx.x;
    if (row >= ROWS) return;
    int s = row / Ll, l = row % Ll;

    // combine attention partials -> ctx
    float cx[Ee];
    #pragma unroll
    for (int h = 0; h < NHh; h++) {
        int combo = l*NHh + h;
        const float4* pp = g_part + (combo*Ss + s)*NTC;
        float4 acc = pp[0];
        #pragma unroll
        for (int tc = 1; tc < NTC; tc++) {
            float4 q = pp[tc];
            acc.x += q.x; acc.y += q.y; acc.z += q.z; acc.w += q.w;
        }
        float inv = 1.f / acc.x;
        cx[h*3]   = acc.y * inv;
        cx[h*3+1] = acc.z * inv;
        cx[h*3+2] = acc.w * inv;
    }

    // out_proj + residual + LN1
    float t[Ee]; float mu = 0.f;
    #pragma unroll
    for (int e = 0; e < Ee; e++) {
        float acc = sbo[e];
        #pragma unroll
        for (int f = 0; f < Ee; f++) acc += cx[f] * swo[e*Ee + f];
        t[e] = g_seq[row*Ee + e] + acc;
        mu += t[e];
    }
    mu *= (1.f/Ee);
    float var = 0.f;
    #pragma unroll
    for (int e = 0; e < Ee; e++) { float d = t[e]-mu; var += d*d; }
    var *= (1.f/Ee);
    float rs = rsqrtf(var + 1e-5f);

    float h1[Ee];
    #pragma unroll
    for (int e = 0; e < Ee; e++) h1[e] = (t[e]-mu)*rs*sg1[e] + sb1[e];

    // FFN
    float hid[FFf];
    #pragma unroll
    for (int f = 0; f < FFf; f++) {
        float acc = s1b[f];
        #pragma unroll
        for (int e = 0; e < Ee; e++) acc += h1[e] * s1[f*Ee + e];
        hid[f] = fmaxf(acc, 0.f);
    }

    float mu2 = 0.f;
    #pragma unroll
    for (int e = 0; e < Ee; e++) {
        float acc = s2b[e];
        #pragma unroll
        for (int f = 0; f < FFf; f++) acc += hid[f] * s2[e*FFf + f];
        t[e] = h1[e] + acc;
        mu2 += t[e];
    }
    mu2 *= (1.f/Ee);
    float var2 = 0.f;
    #pragma unroll
    for (int e = 0; e < Ee; e++) { float d = t[e]-mu2; var2 += d*d; }
    var2 *= (1.f/Ee);
    float rs2 = rsqrtf(var2 + 1e-5f);

    float proj = slb;
    #pragma unroll
    for (int e = 0; e < Ee; e++)
        proj += ((t[e]-mu2)*rs2*sg2[e] + sb2[e]) * slw[e];

    // fold: this (s,l) row contributes proj to exactly one output cell
    int b   = s / (Cc*Kk*Kk);
    int rem = s % (Cc*Kk*Kk);
    int c = rem / (Kk*Kk), p = rem % (Kk*Kk);
    int i = p / Kk, j = p % Kk;
    int oi = l / WOo, oj = l % WOo;
    atomicAdd(&y[((b*Cc + c)*Hh + (i+oi))*Ww + (j+oj)], proj);
}

// ---------------- launch ----------------
extern "C" void kernel_launch(void* const* d_in, const int* in_sizes, int n_in,
                              void* d_out, int out_size)
{
    const float* x    = (const float*)d_in[0];
    const float* ce   = (const float*)d_in[1];
    const float* pe   = (const float*)d_in[2];
    const float* ipw  = (const float*)d_in[3];
    const float* ipb  = (const float*)d_in[4];
    const float* opw  = (const float*)d_in[5];
    const float* opb  = (const float*)d_in[6];
    const float* ln1w = (const float*)d_in[7];
    const float* ln1b = (const float*)d_in[8];
    const float* f1w  = (const float*)d_in[9];
    const float* f1b  = (const float*)d_in[10];
    const float* f2w  = (const float*)d_in[11];
    const float* f2b  = (const float*)d_in[12];
    const float* ln2w = (const float*)d_in[13];
    const float* ln2b = (const float*)d_in[14];
    const float* lw   = (const float*)d_in[15];
    const float* lb   = (const float*)d_in[16];
    float* y = (float*)d_out;

    k_embed_qkv<<<ROWS/128, 128>>>(x, ce, pe, ipw, ipb, y);
    dim3 agrid(NC, NQC, NTC);
    k_attn<<<agrid, QPB>>>();
    k_post<<<ROWS/128, 128>>>(opw, opb, ln1w, ln1b, f1w, f1b, f2w, f2b, ln2w, ln2b, lw, lb, y);
}

// round 6
// speedup vs baseline: 1.3344x; 1.0582x over previous
#include <cuda_runtime.h>
#include <math.h>

typedef unsigned long long ull;

// ---------------- problem constants ----------------
#define Bb   4
#define Cc   64
#define Hh   5
#define Ww   5
#define Kk   3
#define Ee   12
#define NHh  4
#define DHh  3
#define FFf  24
#define HOo  3
#define WOo  3
#define Ll   9
#define Ss   (Bb*Cc*Kk*Kk)       // 2304
#define ROWS (Ss*Ll)             // 20736
#define NC   (Ll*NHh)            // 36
#define YSZ  (Bb*Cc*Hh*Ww)       // 6400

// attention tiling
#define QPB   96                 // threads per attn block (3 warps)
#define QPT   8                  // queries per thread (4 packed pairs)
#define NQC   3                  // query chunks  (2304 / (96*8))
#define NTC   8                  // t-splits
#define TCH   (Ss/NTC)           // 288 t per block

// ---------------- scratch ----------------
__device__ float      g_seq[ROWS*Ee];          // l-major rows: row = l*Ss + s
__device__ float      g_q[NC*Ss*DHh];          // scaled by log2(e)/sqrt(3)
__device__ ulonglong2 g_kvd[NC*Ss*3];          // dup-packed: {kx,kx,ky,ky},{kz,kz,vx,vx},{vy,vy,vz,vz}
__device__ float4     g_part[NTC*NC*Ss];       // [tc][combo][s] -> {sum, a0, a1, a2}

// ---------------- packed f32x2 helpers ----------------
__device__ __forceinline__ ull ffma2(ull a, ull b, ull c) {
    ull d; asm("fma.rn.f32x2 %0, %1, %2, %3;" : "=l"(d) : "l"(a), "l"(b), "l"(c)); return d;
}
__device__ __forceinline__ ull fmul2(ull a, ull b) {
    ull d; asm("mul.rn.f32x2 %0, %1, %2;" : "=l"(d) : "l"(a), "l"(b)); return d;
}
__device__ __forceinline__ ull fadd2(ull a, ull b) {
    ull d; asm("add.rn.f32x2 %0, %1, %2;" : "=l"(d) : "l"(a), "l"(b)); return d;
}
__device__ __forceinline__ ull pack2(float lo, float hi) {
    ull d; asm("mov.b64 %0, {%1, %2};" : "=l"(d) : "f"(lo), "f"(hi)); return d;
}
__device__ __forceinline__ void unpack2(ull v, float& lo, float& hi) {
    asm("mov.b64 {%0, %1}, %2;" : "=f"(lo), "=f"(hi) : "l"(v));
}
__device__ __forceinline__ ull ex2pair(ull s) {
    ull r;
    asm("{\n\t"
        ".reg .f32 lo, hi;\n\t"
        "mov.b64 {lo, hi}, %1;\n\t"
        "ex2.approx.f32 lo, lo;\n\t"
        "ex2.approx.f32 hi, hi;\n\t"
        "mov.b64 %0, {lo, hi};\n\t"
        "}" : "=l"(r) : "l"(s));
    return r;
}

// ---------------- kernel 1: unfold + embeddings + QKV projection ----------------
// grid (ROWS/64, 3): blockIdx.y = role (0=q, 1=k, 2=v). Row ids are l-major.
__global__ void k_embed_qkv(const float* __restrict__ x,
                            const float* __restrict__ ce,
                            const float* __restrict__ pe,
                            const float* __restrict__ wqkv,
                            const float* __restrict__ bqkv,
                            float* __restrict__ y)
{
    int role = blockIdx.y;
    __shared__ float sw[Ee*Ee];
    __shared__ float sb[Ee];
    for (int i = threadIdx.x; i < Ee*Ee; i += blockDim.x) sw[i] = wqkv[role*Ee*Ee + i];
    if (threadIdx.x < Ee) sb[threadIdx.x] = bqkv[role*Ee + threadIdx.x];
    __syncthreads();

    int row = blockIdx.x*blockDim.x + threadIdx.x;   // row = l*Ss + s
    if (row >= ROWS) return;
    int l = row / Ss, s = row % Ss;
    int b   = s / (Cc*Kk*Kk);
    int rem = s % (Cc*Kk*Kk);
    int c = rem / (Kk*Kk), p = rem % (Kk*Kk);
    int i = p / Kk, j = p % Kk;
    int oi = l / WOo, oj = l % WOo;

    float xv = x[((b*Cc + c)*Hh + (i+oi))*Ww + (j+oj)];

    float r[Ee];
    #pragma unroll
    for (int e = 0; e < Ee; e++) r[e] = ce[c*Ee + e] + pe[l*Ee + e] + xv;

    if (role == 0) {
        #pragma unroll
        for (int e = 0; e < Ee; e++) g_seq[row*Ee + e] = r[e];
        if (row < YSZ) y[row] = 0.f;    // zero output for later atomics
    }

    float out[Ee];
    #pragma unroll
    for (int e = 0; e < Ee; e++) {
        float acc = sb[e];
        #pragma unroll
        for (int f = 0; f < Ee; f++) acc += r[f] * sw[e*Ee + f];
        out[e] = acc;
    }

    float4* kvd = (float4*)g_kvd;
    if (role == 0) {
        const float qscale = 0.57735026918962576f * 1.4426950408889634f; // 1/sqrt(3)*log2(e)
        #pragma unroll
        for (int h = 0; h < NHh; h++) {
            int base = ((l*NHh + h)*Ss + s)*DHh;
            g_q[base+0] = out[h*3]   * qscale;
            g_q[base+1] = out[h*3+1] * qscale;
            g_q[base+2] = out[h*3+2] * qscale;
        }
    } else if (role == 1) {
        #pragma unroll
        for (int h = 0; h < NHh; h++) {
            int idx = ((l*NHh + h)*Ss + s)*3;
            kvd[idx] = make_float4(out[h*3], out[h*3], out[h*3+1], out[h*3+1]);
            reinterpret_cast<float2*>(kvd + idx + 1)[0] = make_float2(out[h*3+2], out[h*3+2]);
        }
    } else {
        #pragma unroll
        for (int h = 0; h < NHh; h++) {
            int idx = ((l*NHh + h)*Ss + s)*3;
            reinterpret_cast<float2*>(kvd + idx + 1)[1] = make_float2(out[h*3], out[h*3]);
            kvd[idx+2] = make_float4(out[h*3+1], out[h*3+1], out[h*3+2], out[h*3+2]);
        }
    }
}

// ---------------- kernel 2: attention partials ----------------
// grid (36 combos, 3 q-chunks, 8 t-chunks), 96 threads, 8 queries/thread (4 packed pairs).
__global__ void k_attn()
{
    __shared__ ulonglong2 kvs[TCH*3];   // 13.8 KB

    int combo = blockIdx.x;
    int tid   = threadIdx.x;
    int s0 = blockIdx.y*(QPB*QPT) + tid;       // queries s0 + 96*j, j=0..7
    int tb = blockIdx.z*TCH;

    // stage K/V chunk (pre-duplicated pairs)
    {
        const ulonglong2* src = g_kvd + (combo*Ss + tb)*3;
        for (int i = tid; i < TCH*3; i += QPB) kvs[i] = src[i];
    }

    // load 8 queries, pack as 4 pairs
    const float* qg = g_q + (combo*Ss + s0)*DHh;
    ull px[4], py[4], pz[4];
    #pragma unroll
    for (int pq = 0; pq < 4; pq++) {
        const float* qa = qg + (2*pq  )*QPB*DHh;
        const float* qb = qg + (2*pq+1)*QPB*DHh;
        px[pq] = pack2(qa[0], qb[0]);
        py[pq] = pack2(qa[1], qb[1]);
        pz[pq] = pack2(qa[2], qb[2]);
    }

    ull sum[4] = {0,0,0,0};
    ull a0[4]  = {0,0,0,0};
    ull a1[4]  = {0,0,0,0};
    ull a2[4]  = {0,0,0,0};

    __syncthreads();

    #pragma unroll 4
    for (int t = 0; t < TCH; t++) {
        ulonglong2 u0 = kvs[3*t];     // {kx2, ky2}
        ulonglong2 u1 = kvs[3*t+1];   // {kz2, vx2}
        ulonglong2 u2 = kvs[3*t+2];   // {vy2, vz2}

        #pragma unroll
        for (int pq = 0; pq < 4; pq++) {
            ull sc = ffma2(px[pq], u0.x, ffma2(py[pq], u0.y, fmul2(pz[pq], u1.x)));
            ull w  = ex2pair(sc);
            sum[pq] = fadd2(sum[pq], w);
            a0[pq]  = ffma2(w, u1.y, a0[pq]);
            a1[pq]  = ffma2(w, u2.x, a1[pq]);
            a2[pq]  = ffma2(w, u2.y, a2[pq]);
        }
    }

    int tc = blockIdx.z;
    #pragma unroll
    for (int pq = 0; pq < 4; pq++) {
        float sA, sB, x0A, x0B, x1A, x1B, x2A, x2B;
        unpack2(sum[pq], sA, sB);
        unpack2(a0[pq], x0A, x0B);
        unpack2(a1[pq], x1A, x1B);
        unpack2(a2[pq], x2A, x2B);
        int sa = s0 + (2*pq)*QPB;
        g_part[(tc*NC + combo)*Ss + sa      ] = make_float4(sA, x0A, x1A, x2A);
        g_part[(tc*NC + combo)*Ss + sa + QPB] = make_float4(sB, x0B, x1B, x2B);
    }
}

// ---------------- kernel 3: combine + out_proj + LN1 + FFN + LN2 + linear + fold ----------------
__global__ void k_post(const float* __restrict__ wo, const float* __restrict__ bo,
                       const float* __restrict__ g1, const float* __restrict__ b1,
                       const float* __restrict__ f1w, const float* __restrict__ f1b,
                       const float* __restrict__ f2w, const float* __restrict__ f2b,
                       const float* __restrict__ g2, const float* __restrict__ b2,
                       const float* __restrict__ lw, const float* __restrict__ lb,
                       float* __restrict__ y)
{
    __shared__ float swo[Ee*Ee], sbo[Ee], sg1[Ee], sb1[Ee];
    __shared__ float s1[FFf*Ee], s1b[FFf], s2[Ee*FFf], s2b[Ee];
    __shared__ float sg2[Ee], sb2[Ee], slw[Ee], slb;
    for (int i = threadIdx.x; i < Ee*Ee; i += blockDim.x) swo[i] = wo[i];
    for (int i = threadIdx.x; i < FFf*Ee; i += blockDim.x) { s1[i] = f1w[i]; s2[i] = f2w[i]; }
    if (threadIdx.x < FFf) s1b[threadIdx.x] = f1b[threadIdx.x];
    if (threadIdx.x < Ee) {
        sbo[threadIdx.x] = bo[threadIdx.x];
        sg1[threadIdx.x] = g1[threadIdx.x];
        sb1[threadIdx.x] = b1[threadIdx.x];
        s2b[threadIdx.x] = f2b[threadIdx.x];
        sg2[threadIdx.x] = g2[threadIdx.x];
        sb2[threadIdx.x] = b2[threadIdx.x];
        slw[threadIdx.x] = lw[threadIdx.x];
    }
    if (threadIdx.x == 0) slb = lb[0];
    __syncthreads();

    int row = blockIdx.x*blockDim.x + threadIdx.x;   // l-major: row = l*Ss + s
    if (row >= ROWS) return;
    int l = row / Ss, s = row % Ss;

    // combine attention partials -> ctx (coalesced: consecutive threads -> consecutive s)
    float cx[Ee];
    #pragma unroll
    for (int h = 0; h < NHh; h++) {
        int combo = l*NHh + h;
        float4 acc = make_float4(0.f, 0.f, 0.f, 0.f);
        #pragma unroll
        for (int tc = 0; tc < NTC; tc++) {
            float4 q = g_part[(tc*NC + combo)*Ss + s];
            acc.x += q.x; acc.y += q.y; acc.z += q.z; acc.w += q.w;
        }
        float inv = 1.f / acc.x;
        cx[h*3]   = acc.y * inv;
        cx[h*3+1] = acc.z * inv;
        cx[h*3+2] = acc.w * inv;
    }

    // out_proj + residual + LN1
    float t[Ee]; float mu = 0.f;
    #pragma unroll
    for (int e = 0; e < Ee; e++) {
        float acc = sbo[e];
        #pragma unroll
        for (int f = 0; f < Ee; f++) acc += cx[f] * swo[e*Ee + f];
        t[e] = g_seq[row*Ee + e] + acc;
        mu += t[e];
    }
    mu *= (1.f/Ee);
    float var = 0.f;
    #pragma unroll
    for (int e = 0; e < Ee; e++) { float d = t[e]-mu; var += d*d; }
    var *= (1.f/Ee);
    float rs = rsqrtf(var + 1e-5f);

    float h1[Ee];
    #pragma unroll
    for (int e = 0; e < Ee; e++) h1[e] = (t[e]-mu)*rs*sg1[e] + sb1[e];

    // FFN
    float hid[FFf];
    #pragma unroll
    for (int f = 0; f < FFf; f++) {
        float acc = s1b[f];
        #pragma unroll
        for (int e = 0; e < Ee; e++) acc += h1[e] * s1[f*Ee + e];
        hid[f] = fmaxf(acc, 0.f);
    }

    float mu2 = 0.f;
    #pragma unroll
    for (int e = 0; e < Ee; e++) {
        float acc = s2b[e];
        #pragma unroll
        for (int f = 0; f < FFf; f++) acc += hid[f] * s2[e*FFf + f];
        t[e] = h1[e] + acc;
        mu2 += t[e];
    }
    mu2 *= (1.f/Ee);
    float var2 = 0.f;
    #pragma unroll
    for (int e = 0; e < Ee; e++) { float d = t[e]-mu2; var2 += d*d; }
    var2 *= (1.f/Ee);
    float rs2 = rsqrtf(var2 + 1e-5f);

    float proj = slb;
    #pragma unroll
    for (int e = 0; e < Ee; e++)
        proj += ((t[e]-mu2)*rs2*sg2[e] + sb2[e]) * slw[e];

    // fold: this (s,l) row contributes proj to exactly one output cell
    int b   = s / (Cc*Kk*Kk);
    int rem = s % (Cc*Kk*Kk);
    int c = rem / (Kk*Kk), p = rem % (Kk*Kk);
    int i = p / Kk, j = p % Kk;
    int oi = l / WOo, oj = l % WOo;
    atomicAdd(&y[((b*Cc + c)*Hh + (i+oi))*Ww + (j+oj)], proj);
}

// ---------------- launch ----------------
extern "C" void kernel_launch(void* const* d_in, const int* in_sizes, int n_in,
                              void* d_out, int out_size)
{
    const float* x    = (const float*)d_in[0];
    const float* ce   = (const float*)d_in[1];
    const float* pe   = (const float*)d_in[2];
    const float* ipw  = (const float*)d_in[3];
    const float* ipb  = (const float*)d_in[4];
    const float* opw  = (const float*)d_in[5];
    const float* opb  = (const float*)d_in[6];
    const float* ln1w = (const float*)d_in[7];
    const float* ln1b = (const float*)d_in[8];
    const float* f1w  = (const float*)d_in[9];
    const float* f1b  = (const float*)d_in[10];
    const float* f2w  = (const float*)d_in[11];
    const float* f2b  = (const float*)d_in[12];
    const float* ln2w = (const float*)d_in[13];
    const float* ln2b = (const float*)d_in[14];
    const float* lw   = (const float*)d_in[15];
    const float* lb   = (const float*)d_in[16];
    float* y = (float*)d_out;

    dim3 egrid(ROWS/64, 3);
    k_embed_qkv<<<egrid, 64>>>(x, ce, pe, ipw, ipb, y);
    dim3 agrid(NC, NQC, NTC);
    k_attn<<<agrid, QPB>>>();
    k_post<<<ROWS/64, 64>>>(opw, opb, ln1w, ln1b, f1w, f1b, f2w, f2b, ln2w, ln2b, lw, lb, y);
}